// round 13
// baseline (speedup 1.0000x reference)
#include <cuda_runtime.h>
#include <cuda_bf16.h>
#include <cstdint>

#define DVAL 64
#define MAXM 16384
#define MAXN 8192
#define REGP   0.05f
#define LOG2E  1.4426950408889634f
#define LN2    0.6931471805599453f
#define SHIFT  28.0f
#define QS     31.75f            // int8 quant scale (127/4)

#define THREADS 512          // 16 warps
#define BLOCK_ROWS 512       // 32 rows per warp
#define TJ 128               // j-tile
#define JSPLIT 9
#define MAXTILES 15          // ceil(128/9)
#define ONESF 0x3F803F80u    // bf16x2 (1.0, 1.0)
#define TILEB 8192           // int8 j-tile bytes (128 rows x 64)

__device__ double g_cost_sum;
__device__ double g_psi_sum;
__device__ double g_result;
__device__ unsigned int g_done;
__device__ float  g_sqt[MAXM];
__device__ float  g_sqs[MAXN];
__device__ float  g_rowsum[MAXN];
__device__ uint4  g_tgtq[MAXM * 4];   // int8, B-fragment layout (16B per lane slot)
__device__ uint4  g_srcq[MAXN * 4];   // int8, row-major 64B/row

// ---------- helpers ----------
static __device__ __forceinline__ uint32_t cvt_bf16x2(float lo, float hi) {
    uint32_t r; asm("cvt.rn.bf16x2.f32 %0, %1, %2;" : "=r"(r) : "f"(hi), "f"(lo)); return r;
}
static __device__ __forceinline__ uint32_t ex2_bf16x2(uint32_t a) {
    uint32_t r; asm("ex2.approx.ftz.bf16x2 %0, %1;" : "=r"(r) : "r"(a)); return r;
}
// bf16 m16n8k16, C==D accumulate (row-sum reduction)
static __device__ __forceinline__ void mma16816(float* c, const uint32_t* a, uint32_t b0, uint32_t b1) {
    asm("mma.sync.aligned.m16n8k16.row.col.f32.bf16.bf16.f32 "
        "{%0,%1,%2,%3}, {%4,%5,%6,%7}, {%8,%9}, {%0,%1,%2,%3};"
        : "+f"(c[0]), "+f"(c[1]), "+f"(c[2]), "+f"(c[3])
        : "r"(a[0]), "r"(a[1]), "r"(a[2]), "r"(a[3]), "r"(b0), "r"(b1));
}
// int8 m16n8k32, s32 accumulate
static __device__ __forceinline__ void mma_s8(int* c, const uint32_t* a, uint32_t b0, uint32_t b1) {
    asm("mma.sync.aligned.m16n8k32.row.col.s32.s8.s8.s32 "
        "{%0,%1,%2,%3}, {%4,%5,%6,%7}, {%8,%9}, {%0,%1,%2,%3};"
        : "+r"(c[0]), "+r"(c[1]), "+r"(c[2]), "+r"(c[3])
        : "r"(a[0]), "r"(a[1]), "r"(a[2]), "r"(a[3]), "r"(b0), "r"(b1));
}
static __device__ __forceinline__ uint32_t quant4(float4 v) {
    int b0 = __float2int_rn(fminf(fmaxf(v.x * QS, -127.f), 127.f));
    int b1 = __float2int_rn(fminf(fmaxf(v.y * QS, -127.f), 127.f));
    int b2 = __float2int_rn(fminf(fmaxf(v.z * QS, -127.f), 127.f));
    int b3 = __float2int_rn(fminf(fmaxf(v.w * QS, -127.f), 127.f));
    return (uint32_t)(b0 & 0xFF) | ((uint32_t)(b1 & 0xFF) << 8) |
           ((uint32_t)(b2 & 0xFF) << 16) | ((uint32_t)(b3 & 0xFF) << 24);
}
static __device__ __forceinline__ uint32_t smem_u32(const void* p) {
    uint32_t a;
    asm("{ .reg .u64 t; cvta.to.shared.u64 t, %1; cvt.u32.u64 %0, t; }" : "=r"(a) : "l"(p));
    return a;
}
#define CP_ASYNC16(dst, src) \
    asm volatile("cp.async.cg.shared.global [%0], [%1], 16;" :: "r"(dst), "l"(src) : "memory")
#define CP_COMMIT() asm volatile("cp.async.commit_group;" ::: "memory")
#define CP_WAIT0()  asm volatile("cp.async.wait_group 0;" ::: "memory")

// ---------------- kernel 1: quantize + reductions + init ----------------
__global__ void k_pre(const float* __restrict__ src, const float* __restrict__ tgt,
                      const float* __restrict__ psi, int N, int M) {
    int gtid = blockIdx.x * blockDim.x + threadIdx.x;
    int nth  = gridDim.x * blockDim.x;
    int lane = threadIdx.x & 31;

    if (gtid == 0) { g_cost_sum = 0.0; g_psi_sum = 0.0; g_result = 0.0; g_done = 0u; }
    for (int i = gtid; i < N; i += nth) g_rowsum[i] = 0.0f;

    // tgt -> int8 in B-fragment layout + cost_sum
    // slot i: tile tt = i>>9, subtile t = (i>>5)&15, lane l = i&31; n = l>>2, c = l&3
    // row j = tt*128 + t*8 + n; 4 words from cols c*4 + {0,16,32,48}
    float cs = 0.0f;
    const int nB = (M >> 7) * 512;
    for (int i = gtid; i < nB; i += nth) {
        int l = i & 31, t = (i >> 5) & 15, tt = i >> 9;
        int n = l >> 2, c = l & 3;
        int j = tt * 128 + t * 8 + n;
        const float* row = tgt + (size_t)j * DVAL + c * 4;
        uint32_t w[4];
        #pragma unroll
        for (int q = 0; q < 4; ++q) {
            float4 v = *(const float4*)(row + q * 16);
            cs += v.x * v.x + v.y * v.y + v.z * v.z + v.w * v.w;
            w[q] = quant4(v);
        }
        g_tgtq[i] = make_uint4(w[0], w[1], w[2], w[3]);
    }
    // src -> int8 row-major
    for (int i = gtid; i < N * 4; i += nth) {
        int row = i >> 2, ch = i & 3;
        const float4* p = (const float4*)(src + (size_t)row * DVAL + ch * 16);
        uint32_t w[4];
        #pragma unroll
        for (int q = 0; q < 4; ++q) w[q] = quant4(p[q]);
        g_srcq[i] = make_uint4(w[0], w[1], w[2], w[3]);
    }
    float pp = 0.0f;
    for (int i = gtid; i < M; i += nth) pp += psi[i];
    #pragma unroll
    for (int o = 16; o; o >>= 1) {
        cs += __shfl_xor_sync(0xffffffffu, cs, o);
        pp += __shfl_xor_sync(0xffffffffu, pp, o);
    }
    if (lane == 0) {
        atomicAdd(&g_cost_sum, (double)cs);
        if (pp != 0.0f) atomicAdd(&g_psi_sum, (double)pp);
    }

    // per-row squared norms (exact f32), 4 lanes per row
    int grp = gtid >> 2, sub = gtid & 3, ngrp = nth >> 2;
    for (int row = grp; row < M + N; row += ngrp) {
        const float4* p = (row < M)
            ? (const float4*)(tgt + (size_t)row * DVAL)
            : (const float4*)(src + (size_t)(row - M) * DVAL);
        float s = 0.0f;
        #pragma unroll
        for (int q = 0; q < 4; ++q) {
            float4 v = p[sub + q * 4];
            s += v.x * v.x + v.y * v.y + v.z * v.z + v.w * v.w;
        }
        s += __shfl_xor_sync(0xffffffffu, s, 1);
        s += __shfl_xor_sync(0xffffffffu, s, 2);
        if (sub == 0) {
            if (row < M) g_sqt[row] = s; else g_sqs[row - M] = s;
        }
    }
}

// ---------------- kernel 2: int8 IMMA + bf16x2 exp2 + mma-reduction ----------------
__global__ void __launch_bounds__(THREADS, 1)
k_main_mma(const float* __restrict__ psi, float* __restrict__ out, int N, int M) {
    __shared__ char sm[2 * TILEB + MAXTILES * TJ * 4];
    __shared__ int smflag;
    float* sbias = (float*)(sm + 2 * TILEB);
    const uint32_t smb = smem_u32(sm);

    const int tid  = threadIdx.x;
    const int wid  = tid >> 5;
    const int lane = tid & 31;
    const int g    = lane >> 2;     // fragment row group
    const int c    = lane & 3;      // fragment k group

    const int rbase = blockIdx.x * BLOCK_ROWS + wid * 32;

    const int TT = M / TJ;
    const int tbeg = (blockIdx.y * TT) / JSPLIT;
    const int tend = ((blockIdx.y + 1) * TT) / JSPLIT;
    const int jbase = tbeg * TJ;
    const int jcnt  = (tend - tbeg) * TJ;

    const char* tgtq_bytes = (const char*)g_tgtq;

    // ---- start tile 0 fill: 512 threads x 16B = 8KB, linear copy ----
    CP_ASYNC16(smb + tid * 16, tgtq_bytes + (size_t)tbeg * TILEB + tid * 16);
    CP_COMMIT();

    const float cn = (float)(g_cost_sum / (double)M);
    const float alpha = 1.0f / (REGP * cn);
    const float k1q = 2.0f * LOG2E * alpha / (QS * QS);

    // ---- bias for whole j-range into smem (overlaps cp.async) ----
    for (int jj = tid; jj < jcnt; jj += THREADS) {
        int j = jbase + jj;
        sbias[jj] = LOG2E * (psi[j] * (1.0f / REGP) - alpha * g_sqt[j]) + SHIFT;
    }

    // ---- A fragments (int8): [rowtile][kmma][a0..a3] ----
    uint32_t afr[2][2][4];
    {
        #pragma unroll
        for (int rt = 0; rt < 2; ++rt) {
            const uint32_t* p0 = (const uint32_t*)((const char*)g_srcq
                                 + (size_t)(rbase + rt * 16 + g) * DVAL + c * 4);
            const uint32_t* p1 = (const uint32_t*)((const char*)g_srcq
                                 + (size_t)(rbase + rt * 16 + g + 8) * DVAL + c * 4);
            #pragma unroll
            for (int q = 0; q < 2; ++q) {
                afr[rt][q][0] = p0[q * 8];        // row g,   k-base + c*4
                afr[rt][q][1] = p1[q * 8];        // row g+8
                afr[rt][q][2] = p0[q * 8 + 4];    // row g,   +16 cols
                afr[rt][q][3] = p1[q * 8 + 4];
            }
        }
    }

    const int biasoff = c * 2;

    // f32 row-sum accumulators fed by the reduction MMA
    float acc0[4] = {0.f, 0.f, 0.f, 0.f};   // rows g, g+8
    float acc1[4] = {0.f, 0.f, 0.f, 0.f};   // rows g+16, g+24

    for (int t = tbeg; t < tend; ++t) {
        const int cur = (t - tbeg) & 1, nxt = cur ^ 1;
        const bool more = (t + 1 < tend);

        CP_WAIT0();
        __syncthreads();

        if (more) {
            CP_ASYNC16(smb + (uint32_t)(nxt * TILEB) + tid * 16,
                       tgtq_bytes + (size_t)(t + 1) * TILEB + tid * 16);
            CP_COMMIT();
        }

        const char* tb = sm + cur * TILEB;
        const float* bb = sbias + (t - tbeg) * TJ;
        #pragma unroll 2
        for (int sp = 0; sp < 8; ++sp) {
            uint32_t eA[4], eB[4];   // bf16x2 exps: A-fragments for reduction mma
            #pragma unroll
            for (int h = 0; h < 2; ++h) {
                const int s = sp * 2 + h;
                // one LDS.128 = full B fragment for both k-halves of this n8-subtile
                uint4 w = *(const uint4*)(tb + s * 512 + lane * 16);
                int ci0[4] = {0, 0, 0, 0};
                int ci1[4] = {0, 0, 0, 0};
                mma_s8(ci0, afr[0][0], w.x, w.y);
                mma_s8(ci1, afr[1][0], w.x, w.y);
                mma_s8(ci0, afr[0][1], w.z, w.w);
                mma_s8(ci1, afr[1][1], w.z, w.w);

                const float2 bp = *(const float2*)(bb + s * 8 + biasoff);
                float x0 = fmaf((float)ci0[0], k1q, bp.x);
                float x1 = fmaf((float)ci0[1], k1q, bp.y);
                float x2 = fmaf((float)ci0[2], k1q, bp.x);
                float x3 = fmaf((float)ci0[3], k1q, bp.y);
                float x4 = fmaf((float)ci1[0], k1q, bp.x);
                float x5 = fmaf((float)ci1[1], k1q, bp.y);
                float x6 = fmaf((float)ci1[2], k1q, bp.x);
                float x7 = fmaf((float)ci1[3], k1q, bp.y);
                eA[h * 2 + 0] = ex2_bf16x2(cvt_bf16x2(x0, x1));   // row g
                eA[h * 2 + 1] = ex2_bf16x2(cvt_bf16x2(x2, x3));   // row g+8
                eB[h * 2 + 0] = ex2_bf16x2(cvt_bf16x2(x4, x5));   // row g+16
                eB[h * 2 + 1] = ex2_bf16x2(cvt_bf16x2(x6, x7));   // row g+24
            }
            // row-sum via tensor pipe: C[m,n] += sum_k E[m,k] * 1
            mma16816(acc0, eA, ONESF, ONESF);
            mma16816(acc1, eB, ONESF, ONESF);
        }
        __syncthreads();
    }

    // ---- per-row accumulation: acc[0]/acc[2] hold full row sums (4 lanes identical) ----
    if (c == 0) {
        atomicAdd(&g_rowsum[rbase + g],      acc0[0]);
        atomicAdd(&g_rowsum[rbase + 8 + g],  acc0[2]);
        atomicAdd(&g_rowsum[rbase + 16 + g], acc1[0]);
        atomicAdd(&g_rowsum[rbase + 24 + g], acc1[2]);
    }

    // ---- inline finalize: last CTA reduces all rows ----
    __syncthreads();
    if (tid == 0) {
        __threadfence();
        unsigned int old = atomicAdd(&g_done, 1u);
        smflag = (old == (unsigned int)(gridDim.x * gridDim.y - 1)) ? 1 : 0;
    }
    __syncthreads();
    if (smflag) {
        const float log_nu = -logf((float)M);
        double part = 0.0;
        for (int i = tid; i < N; i += THREADS) {
            float lse = -alpha * g_sqs[i] + log_nu + LN2 * (log2f(g_rowsum[i]) - SHIFT);
            part += (double)(-REGP * lse);
        }
        #pragma unroll
        for (int o = 16; o; o >>= 1) part += __shfl_xor_sync(0xffffffffu, part, o);
        if (lane == 0) atomicAdd(&g_result, part);
        __syncthreads();
        if (tid == 0)
            out[0] = (float)(g_result / (double)N + g_psi_sum / (double)M);
    }
}

extern "C" void kernel_launch(void* const* d_in, const int* in_sizes, int n_in,
                              void* d_out, int out_size) {
    const float* src = (const float*)d_in[0];   // [N, 64]
    const float* tgt = (const float*)d_in[1];   // [M, 64]
    const float* psi = (const float*)d_in[2];   // [M]
    int N = in_sizes[0] / DVAL;
    int M = in_sizes[2];

    k_pre<<<296, 256>>>(src, tgt, psi, N, M);

    dim3 grd(N / BLOCK_ROWS, JSPLIT);           // 16 x 9 = 144 CTAs, 1/SM
    k_main_mma<<<grd, THREADS>>>(psi, (float*)d_out, N, M);
}

// round 14
// speedup vs baseline: 2.2256x; 2.2256x over previous
#include <cuda_runtime.h>
#include <cuda_bf16.h>
#include <cstdint>

#define DVAL 64
#define MAXM 16384
#define MAXN 8192
#define REGP   0.05f
#define LOG2E  1.4426950408889634f
#define LN2    0.6931471805599453f
#define SHIFT  28.0f

#define THREADS 512          // 16 warps
#define BLOCK_ROWS 512       // 32 rows per warp
#define TJ 128               // j-tile
#define JSPLIT 9
#define MAXTILES 15          // ceil(128/9)
#define ONESF 0x3F803F80u    // bf16x2 (1.0, 1.0)

__device__ double g_cost_sum;
__device__ double g_psi_sum;
__device__ double g_result;
__device__ unsigned int g_done;
__device__ float  g_sqt[MAXM];
__device__ float  g_sqs[MAXN];
__device__ float  g_rowsum[MAXN];
__device__ uint32_t g_tgtb[MAXM * DVAL / 2];   // bf16x2 packed
__device__ uint32_t g_srcb[MAXN * DVAL / 2];

// ---------- helpers ----------
static __device__ __forceinline__ uint32_t cvt_bf16x2(float lo, float hi) {
    uint32_t r; asm("cvt.rn.bf16x2.f32 %0, %1, %2;" : "=r"(r) : "f"(hi), "f"(lo)); return r;
}
static __device__ __forceinline__ uint32_t ex2_bf16x2(uint32_t a) {
    uint32_t r; asm("ex2.approx.ftz.bf16x2 %0, %1;" : "=r"(r) : "r"(a)); return r;
}
// D += A*B (C == D)
static __device__ __forceinline__ void mma16816(float* c, const uint32_t* a, uint32_t b0, uint32_t b1) {
    asm("mma.sync.aligned.m16n8k16.row.col.f32.bf16.bf16.f32 "
        "{%0,%1,%2,%3}, {%4,%5,%6,%7}, {%8,%9}, {%0,%1,%2,%3};"
        : "+f"(c[0]), "+f"(c[1]), "+f"(c[2]), "+f"(c[3])
        : "r"(a[0]), "r"(a[1]), "r"(a[2]), "r"(a[3]), "r"(b0), "r"(b1));
}
// D = A*B + C (separate C)
static __device__ __forceinline__ void mma16816_dc(float* d, const uint32_t* a, uint32_t b0, uint32_t b1,
                                                   const float* c) {
    asm("mma.sync.aligned.m16n8k16.row.col.f32.bf16.bf16.f32 "
        "{%0,%1,%2,%3}, {%4,%5,%6,%7}, {%8,%9}, {%10,%11,%12,%13};"
        : "=f"(d[0]), "=f"(d[1]), "=f"(d[2]), "=f"(d[3])
        : "r"(a[0]), "r"(a[1]), "r"(a[2]), "r"(a[3]), "r"(b0), "r"(b1),
          "f"(c[0]), "f"(c[1]), "f"(c[2]), "f"(c[3]));
}
static __device__ __forceinline__ void ldm_x4(uint32_t* r, uint32_t addr) {
    asm volatile("ldmatrix.sync.aligned.m8n8.x4.shared.b16 {%0,%1,%2,%3}, [%4];"
        : "=r"(r[0]), "=r"(r[1]), "=r"(r[2]), "=r"(r[3]) : "r"(addr));
}
static __device__ __forceinline__ uint32_t smem_u32(const void* p) {
    uint32_t a;
    asm("{ .reg .u64 t; cvta.to.shared.u64 t, %1; cvt.u32.u64 %0, t; }" : "=r"(a) : "l"(p));
    return a;
}
#define CP_ASYNC16(dst, src) \
    asm volatile("cp.async.cg.shared.global [%0], [%1], 16;" :: "r"(dst), "l"(src) : "memory")
#define CP_COMMIT() asm volatile("cp.async.commit_group;" ::: "memory")
#define CP_WAIT0()  asm volatile("cp.async.wait_group 0;" ::: "memory")

// ---------------- kernel 1: convert + reductions + init ----------------
__global__ void k_pre(const float* __restrict__ src, const float* __restrict__ tgt,
                      const float* __restrict__ psi, int N, int M) {
    int gtid = blockIdx.x * blockDim.x + threadIdx.x;
    int nth  = gridDim.x * blockDim.x;
    int lane = threadIdx.x & 31;

    if (gtid == 0) { g_cost_sum = 0.0; g_psi_sum = 0.0; g_result = 0.0; g_done = 0u; }
    for (int i = gtid; i < N; i += nth) g_rowsum[i] = 0.0f;

    const float2* t2 = (const float2*)tgt;
    float cs = 0.0f;
    for (int i = gtid; i < M * 32; i += nth) {
        float2 v = t2[i];
        cs += v.x * v.x + v.y * v.y;
        g_tgtb[i] = cvt_bf16x2(v.x, v.y);
    }
    const float2* s2 = (const float2*)src;
    for (int i = gtid; i < N * 32; i += nth) {
        float2 v = s2[i];
        g_srcb[i] = cvt_bf16x2(v.x, v.y);
    }
    float pp = 0.0f;
    for (int i = gtid; i < M; i += nth) pp += psi[i];
    #pragma unroll
    for (int o = 16; o; o >>= 1) {
        cs += __shfl_xor_sync(0xffffffffu, cs, o);
        pp += __shfl_xor_sync(0xffffffffu, pp, o);
    }
    if (lane == 0) {
        atomicAdd(&g_cost_sum, (double)cs);
        if (pp != 0.0f) atomicAdd(&g_psi_sum, (double)pp);
    }

    // per-row squared norms, 4 lanes per row
    int grp = gtid >> 2, sub = gtid & 3, ngrp = nth >> 2;
    for (int row = grp; row < M + N; row += ngrp) {
        const float4* p = (row < M)
            ? (const float4*)(tgt + (size_t)row * DVAL)
            : (const float4*)(src + (size_t)(row - M) * DVAL);
        float s = 0.0f;
        #pragma unroll
        for (int q = 0; q < 4; ++q) {
            float4 v = p[sub + q * 4];
            s += v.x * v.x + v.y * v.y + v.z * v.z + v.w * v.w;
        }
        s += __shfl_xor_sync(0xffffffffu, s, 1);
        s += __shfl_xor_sync(0xffffffffu, s, 2);
        if (sub == 0) {
            if (row < M) g_sqt[row] = s; else g_sqs[row - M] = s;
        }
    }
}

// ---------------- kernel 2: main HMMA (split chains + ldm pipeline) ----------------
__global__ void __launch_bounds__(THREADS, 1)
k_main_mma(const float* __restrict__ psi, float* __restrict__ out, int N, int M) {
    __shared__ char sm[2 * 16384 + MAXTILES * TJ * 4];
    __shared__ int smflag;
    float* sbias = (float*)(sm + 32768);
    const uint32_t smb = smem_u32(sm);

    const int tid  = threadIdx.x;
    const int wid  = tid >> 5;
    const int lane = tid & 31;
    const int g    = lane >> 2;

    const int rbase = blockIdx.x * BLOCK_ROWS + wid * 32;

    const int TT = M / TJ;
    const int tbeg = (blockIdx.y * TT) / JSPLIT;
    const int tend = ((blockIdx.y + 1) * TT) / JSPLIT;
    const int jbase = tbeg * TJ;
    const int jcnt  = (tend - tbeg) * TJ;

    // per-thread cp.async chunk coords (2 chunks of 16B per thread)
    const int ch0 = tid,       r0 = ch0 >> 3, c0 = ch0 & 7;
    const int ch1 = tid + 512, r1 = ch1 >> 3, c1 = ch1 & 7;
    const uint32_t d0 = (uint32_t)((r0 * 128 + c0 * 16) ^ ((r0 & 7) << 4));
    const uint32_t d1 = (uint32_t)((r1 * 128 + c1 * 16) ^ ((r1 & 7) << 4));
    const char* tgtb_bytes = (const char*)g_tgtb;

    // ---- start tile 0 fill ----
    CP_ASYNC16(smb + d0, tgtb_bytes + (size_t)(jbase + r0) * 128 + c0 * 16);
    CP_ASYNC16(smb + d1, tgtb_bytes + (size_t)(jbase + r1) * 128 + c1 * 16);
    CP_COMMIT();

    const float cn = (float)(g_cost_sum / (double)M);
    const float alpha = 1.0f / (REGP * cn);
    const float k1 = 2.0f * LOG2E * alpha;

    // ---- bias for whole j-range into smem (overlaps cp.async) ----
    for (int jj = tid; jj < jcnt; jj += THREADS) {
        int j = jbase + jj;
        sbias[jj] = LOG2E * (psi[j] * (1.0f / REGP) - alpha * g_sqt[j]) + SHIFT;
    }

    // ---- A fragments from bf16 globals, prescaled by k1 ----
    uint32_t afr[2][4][4];
    {
        const uint32_t* xb = g_srcb + (size_t)rbase * 32;
        #pragma unroll
        for (int t = 0; t < 2; ++t) {
            #pragma unroll
            for (int ks = 0; ks < 4; ++ks) {
                const uint32_t* p = xb + (t * 16 + g) * 32 + ks * 8 + (lane & 3);
                afr[t][ks][0] = p[0];
                afr[t][ks][1] = p[256];
                afr[t][ks][2] = p[4];
                afr[t][ks][3] = p[260];
                #pragma unroll
                for (int i = 0; i < 4; ++i) {
                    uint32_t u = afr[t][ks][i];
                    float lo = __uint_as_float(u << 16);
                    float hi = __uint_as_float(u & 0xFFFF0000u);
                    afr[t][ks][i] = cvt_bf16x2(lo * k1, hi * k1);
                }
            }
        }
    }

    // ldmatrix per-lane addresses (s-invariant swizzle)
    const int lr = lane & 7, lq = lane >> 3;
    const uint32_t lmoff0 = (uint32_t)(lr * 128 + ((lq * 16)       ^ (lr << 4)));
    const uint32_t lmoff1 = (uint32_t)(lr * 128 + (((lq + 4) * 16) ^ (lr << 4)));
    const int biasoff = (lane & 3) * 2;
    const float zero4[4] = {0.f, 0.f, 0.f, 0.f};

    // f32 row-sum accumulators fed by the reduction MMA
    float acc0[4] = {0.f, 0.f, 0.f, 0.f};   // rows g, g+8
    float acc1[4] = {0.f, 0.f, 0.f, 0.f};   // rows g+16, g+24

    for (int t = tbeg; t < tend; ++t) {
        const int cur = (t - tbeg) & 1, nxt = cur ^ 1;
        const bool more = (t + 1 < tend);

        CP_WAIT0();
        __syncthreads();

        if (more) {
            int j0 = (t + 1) * TJ;
            uint32_t dst = smb + (uint32_t)(nxt * 16384);
            CP_ASYNC16(dst + d0, tgtb_bytes + (size_t)(j0 + r0) * 128 + c0 * 16);
            CP_ASYNC16(dst + d1, tgtb_bytes + (size_t)(j0 + r1) * 128 + c1 * 16);
            CP_COMMIT();
        }

        const uint32_t tadd = smb + (uint32_t)(cur * 16384);
        const float* bb = sbias + (t - tbeg) * TJ;

        // software-pipelined B-fragment loads (double buffer)
        uint32_t fA0[4], fB0[4], fA1[4], fB1[4];
        ldm_x4(fA0, tadd + lmoff0);
        ldm_x4(fB0, tadd + lmoff1);
        uint32_t eA[4], eB[4];

        #pragma unroll
        for (int s = 0; s < 16; s += 2) {
            // prefetch s+1 fragments while computing s
            ldm_x4(fA1, tadd + (s + 1) * 1024 + lmoff0);
            ldm_x4(fB1, tadd + (s + 1) * 1024 + lmoff1);
            {
                const float2 bp = *(const float2*)(bb + s * 8 + biasoff);
                const float bias4[4] = { bp.x, bp.y, bp.x, bp.y };
                float ca0[4], cb0[4], ca1[4], cb1[4];
                mma16816_dc(ca0, afr[0][0], fA0[0], fA0[1], bias4);
                mma16816_dc(ca1, afr[1][0], fA0[0], fA0[1], bias4);
                mma16816_dc(cb0, afr[0][2], fB0[0], fB0[1], zero4);
                mma16816_dc(cb1, afr[1][2], fB0[0], fB0[1], zero4);
                mma16816(ca0, afr[0][1], fA0[2], fA0[3]);
                mma16816(ca1, afr[1][1], fA0[2], fA0[3]);
                mma16816(cb0, afr[0][3], fB0[2], fB0[3]);
                mma16816(cb1, afr[1][3], fB0[2], fB0[3]);
                eA[0] = ex2_bf16x2(cvt_bf16x2(ca0[0] + cb0[0], ca0[1] + cb0[1]));  // row g
                eA[1] = ex2_bf16x2(cvt_bf16x2(ca0[2] + cb0[2], ca0[3] + cb0[3]));  // row g+8
                eB[0] = ex2_bf16x2(cvt_bf16x2(ca1[0] + cb1[0], ca1[1] + cb1[1]));  // row g+16
                eB[1] = ex2_bf16x2(cvt_bf16x2(ca1[2] + cb1[2], ca1[3] + cb1[3]));  // row g+24
            }
            // prefetch s+2 fragments (overwrite buffer 0) while computing s+1
            if (s + 2 < 16) {
                ldm_x4(fA0, tadd + (s + 2) * 1024 + lmoff0);
                ldm_x4(fB0, tadd + (s + 2) * 1024 + lmoff1);
            }
            {
                const float2 bp = *(const float2*)(bb + (s + 1) * 8 + biasoff);
                const float bias4[4] = { bp.x, bp.y, bp.x, bp.y };
                float ca0[4], cb0[4], ca1[4], cb1[4];
                mma16816_dc(ca0, afr[0][0], fA1[0], fA1[1], bias4);
                mma16816_dc(ca1, afr[1][0], fA1[0], fA1[1], bias4);
                mma16816_dc(cb0, afr[0][2], fB1[0], fB1[1], zero4);
                mma16816_dc(cb1, afr[1][2], fB1[0], fB1[1], zero4);
                mma16816(ca0, afr[0][1], fA1[2], fA1[3]);
                mma16816(ca1, afr[1][1], fA1[2], fA1[3]);
                mma16816(cb0, afr[0][3], fB1[2], fB1[3]);
                mma16816(cb1, afr[1][3], fB1[2], fB1[3]);
                eA[2] = ex2_bf16x2(cvt_bf16x2(ca0[0] + cb0[0], ca0[1] + cb0[1]));
                eA[3] = ex2_bf16x2(cvt_bf16x2(ca0[2] + cb0[2], ca0[3] + cb0[3]));
                eB[2] = ex2_bf16x2(cvt_bf16x2(ca1[0] + cb1[0], ca1[1] + cb1[1]));
                eB[3] = ex2_bf16x2(cvt_bf16x2(ca1[2] + cb1[2], ca1[3] + cb1[3]));
            }
            // row-sum via tensor pipe (B = ones; k-permutation irrelevant to the sum)
            mma16816(acc0, eA, ONESF, ONESF);
            mma16816(acc1, eB, ONESF, ONESF);
        }
        __syncthreads();
    }

    // ---- per-row accumulation: acc[0]/acc[2] hold full row sums (4 lanes identical) ----
    if ((lane & 3) == 0) {
        atomicAdd(&g_rowsum[rbase + g],      acc0[0]);
        atomicAdd(&g_rowsum[rbase + 8 + g],  acc0[2]);
        atomicAdd(&g_rowsum[rbase + 16 + g], acc1[0]);
        atomicAdd(&g_rowsum[rbase + 24 + g], acc1[2]);
    }

    // ---- inline finalize: last CTA reduces all rows ----
    __syncthreads();
    if (tid == 0) {
        __threadfence();
        unsigned int old = atomicAdd(&g_done, 1u);
        smflag = (old == (unsigned int)(gridDim.x * gridDim.y - 1)) ? 1 : 0;
    }
    __syncthreads();
    if (smflag) {
        const float log_nu = -logf((float)M);
        double part = 0.0;
        for (int i = tid; i < N; i += THREADS) {
            float lse = -alpha * g_sqs[i] + log_nu + LN2 * (log2f(g_rowsum[i]) - SHIFT);
            part += (double)(-REGP * lse);
        }
        #pragma unroll
        for (int o = 16; o; o >>= 1) part += __shfl_xor_sync(0xffffffffu, part, o);
        if (lane == 0) atomicAdd(&g_result, part);
        __syncthreads();
        if (tid == 0)
            out[0] = (float)(g_result / (double)N + g_psi_sum / (double)M);
    }
}

extern "C" void kernel_launch(void* const* d_in, const int* in_sizes, int n_in,
                              void* d_out, int out_size) {
    const float* src = (const float*)d_in[0];   // [N, 64]
    const float* tgt = (const float*)d_in[1];   // [M, 64]
    const float* psi = (const float*)d_in[2];   // [M]
    int N = in_sizes[0] / DVAL;
    int M = in_sizes[2];

    k_pre<<<296, 256>>>(src, tgt, psi, N, M);

    dim3 grd(N / BLOCK_ROWS, JSPLIT);           // 16 x 9 = 144 CTAs, 1/SM
    k_main_mma<<<grd, THREADS>>>(psi, (float*)d_out, N, M);
}

// round 15
// speedup vs baseline: 2.2792x; 1.0241x over previous
#include <cuda_runtime.h>
#include <cuda_bf16.h>
#include <cstdint>

#define DVAL 64
#define MAXM 16384
#define MAXN 8192
#define REGP   0.05f
#define LOG2E  1.4426950408889634f
#define LN2    0.6931471805599453f
#define SHIFT  28.0f

#define THREADS 512          // 16 warps
#define BLOCK_ROWS 512       // 32 rows per warp
#define TJ 128               // j-tile
#define JSPLIT 9
#define MAXTILES 15          // ceil(128/9)
#define ONESF 0x3F803F80u    // bf16x2 (1.0, 1.0)

__device__ double g_cost_sum;
__device__ double g_psi_sum;
__device__ double g_result;
__device__ unsigned int g_done;
__device__ float  g_sqt[MAXM];
__device__ float  g_sqs[MAXN];
__device__ float  g_rowsum[MAXN];
__device__ uint32_t g_tgtb[MAXM * DVAL / 2];   // bf16x2 packed
__device__ uint32_t g_srcb[MAXN * DVAL / 2];

// ---------- helpers ----------
static __device__ __forceinline__ uint32_t cvt_bf16x2(float lo, float hi) {
    uint32_t r; asm("cvt.rn.bf16x2.f32 %0, %1, %2;" : "=r"(r) : "f"(hi), "f"(lo)); return r;
}
static __device__ __forceinline__ float ex2f(float x) {
    float r; asm("ex2.approx.ftz.f32 %0, %1;" : "=f"(r) : "f"(x)); return r;
}
// D += A*B (C == D)
static __device__ __forceinline__ void mma16816(float* c, const uint32_t* a, uint32_t b0, uint32_t b1) {
    asm("mma.sync.aligned.m16n8k16.row.col.f32.bf16.bf16.f32 "
        "{%0,%1,%2,%3}, {%4,%5,%6,%7}, {%8,%9}, {%0,%1,%2,%3};"
        : "+f"(c[0]), "+f"(c[1]), "+f"(c[2]), "+f"(c[3])
        : "r"(a[0]), "r"(a[1]), "r"(a[2]), "r"(a[3]), "r"(b0), "r"(b1));
}
// D = A*B + C (separate C: bias-fused first k-step)
static __device__ __forceinline__ void mma16816_dc(float* d, const uint32_t* a, uint32_t b0, uint32_t b1,
                                                   const float* c) {
    asm("mma.sync.aligned.m16n8k16.row.col.f32.bf16.bf16.f32 "
        "{%0,%1,%2,%3}, {%4,%5,%6,%7}, {%8,%9}, {%10,%11,%12,%13};"
        : "=f"(d[0]), "=f"(d[1]), "=f"(d[2]), "=f"(d[3])
        : "r"(a[0]), "r"(a[1]), "r"(a[2]), "r"(a[3]), "r"(b0), "r"(b1),
          "f"(c[0]), "f"(c[1]), "f"(c[2]), "f"(c[3]));
}
static __device__ __forceinline__ void ldm_x4(uint32_t* r, uint32_t addr) {
    asm volatile("ldmatrix.sync.aligned.m8n8.x4.shared.b16 {%0,%1,%2,%3}, [%4];"
        : "=r"(r[0]), "=r"(r[1]), "=r"(r[2]), "=r"(r[3]) : "r"(addr));
}
static __device__ __forceinline__ uint32_t smem_u32(const void* p) {
    uint32_t a;
    asm("{ .reg .u64 t; cvta.to.shared.u64 t, %1; cvt.u32.u64 %0, t; }" : "=r"(a) : "l"(p));
    return a;
}
#define CP_ASYNC16(dst, src) \
    asm volatile("cp.async.cg.shared.global [%0], [%1], 16;" :: "r"(dst), "l"(src) : "memory")
#define CP_COMMIT() asm volatile("cp.async.commit_group;" ::: "memory")
#define CP_WAIT0()  asm volatile("cp.async.wait_group 0;" ::: "memory")

// ---------------- kernel 1: convert + reductions + init ----------------
__global__ void k_pre(const float* __restrict__ src, const float* __restrict__ tgt,
                      const float* __restrict__ psi, int N, int M) {
    int gtid = blockIdx.x * blockDim.x + threadIdx.x;
    int nth  = gridDim.x * blockDim.x;
    int lane = threadIdx.x & 31;

    if (gtid == 0) { g_cost_sum = 0.0; g_psi_sum = 0.0; g_result = 0.0; g_done = 0u; }
    for (int i = gtid; i < N; i += nth) g_rowsum[i] = 0.0f;

    const float2* t2 = (const float2*)tgt;
    float cs = 0.0f;
    for (int i = gtid; i < M * 32; i += nth) {
        float2 v = t2[i];
        cs += v.x * v.x + v.y * v.y;
        g_tgtb[i] = cvt_bf16x2(v.x, v.y);
    }
    const float2* s2 = (const float2*)src;
    for (int i = gtid; i < N * 32; i += nth) {
        float2 v = s2[i];
        g_srcb[i] = cvt_bf16x2(v.x, v.y);
    }
    float pp = 0.0f;
    for (int i = gtid; i < M; i += nth) pp += psi[i];
    #pragma unroll
    for (int o = 16; o; o >>= 1) {
        cs += __shfl_xor_sync(0xffffffffu, cs, o);
        pp += __shfl_xor_sync(0xffffffffu, pp, o);
    }
    if (lane == 0) {
        atomicAdd(&g_cost_sum, (double)cs);
        if (pp != 0.0f) atomicAdd(&g_psi_sum, (double)pp);
    }

    // per-row squared norms, 4 lanes per row
    int grp = gtid >> 2, sub = gtid & 3, ngrp = nth >> 2;
    for (int row = grp; row < M + N; row += ngrp) {
        const float4* p = (row < M)
            ? (const float4*)(tgt + (size_t)row * DVAL)
            : (const float4*)(src + (size_t)(row - M) * DVAL);
        float s = 0.0f;
        #pragma unroll
        for (int q = 0; q < 4; ++q) {
            float4 v = p[sub + q * 4];
            s += v.x * v.x + v.y * v.y + v.z * v.z + v.w * v.w;
        }
        s += __shfl_xor_sync(0xffffffffu, s, 1);
        s += __shfl_xor_sync(0xffffffffu, s, 2);
        if (sub == 0) {
            if (row < M) g_sqt[row] = s; else g_sqs[row - M] = s;
        }
    }
}

// ---------------- kernel 2: main HMMA + f32 exp2 + mma-reduction ----------------
__global__ void __launch_bounds__(THREADS, 1)
k_main_mma(const float* __restrict__ psi, float* __restrict__ out, int N, int M) {
    __shared__ char sm[2 * 16384 + MAXTILES * TJ * 4];
    __shared__ int smflag;
    float* sbias = (float*)(sm + 32768);
    const uint32_t smb = smem_u32(sm);

    const int tid  = threadIdx.x;
    const int wid  = tid >> 5;
    const int lane = tid & 31;
    const int g    = lane >> 2;

    const int rbase = blockIdx.x * BLOCK_ROWS + wid * 32;

    const int TT = M / TJ;
    const int tbeg = (blockIdx.y * TT) / JSPLIT;
    const int tend = ((blockIdx.y + 1) * TT) / JSPLIT;
    const int jbase = tbeg * TJ;
    const int jcnt  = (tend - tbeg) * TJ;

    // per-thread cp.async chunk coords (2 chunks of 16B per thread)
    const int ch0 = tid,       r0 = ch0 >> 3, c0 = ch0 & 7;
    const int ch1 = tid + 512, r1 = ch1 >> 3, c1 = ch1 & 7;
    const uint32_t d0 = (uint32_t)((r0 * 128 + c0 * 16) ^ ((r0 & 7) << 4));
    const uint32_t d1 = (uint32_t)((r1 * 128 + c1 * 16) ^ ((r1 & 7) << 4));
    const char* tgtb_bytes = (const char*)g_tgtb;

    // ---- start tile 0 fill ----
    CP_ASYNC16(smb + d0, tgtb_bytes + (size_t)(jbase + r0) * 128 + c0 * 16);
    CP_ASYNC16(smb + d1, tgtb_bytes + (size_t)(jbase + r1) * 128 + c1 * 16);
    CP_COMMIT();

    const float cn = (float)(g_cost_sum / (double)M);
    const float alpha = 1.0f / (REGP * cn);
    const float k1 = 2.0f * LOG2E * alpha;

    // ---- bias for whole j-range into smem (overlaps cp.async) ----
    for (int jj = tid; jj < jcnt; jj += THREADS) {
        int j = jbase + jj;
        sbias[jj] = LOG2E * (psi[j] * (1.0f / REGP) - alpha * g_sqt[j]) + SHIFT;
    }

    // ---- A fragments from bf16 globals, prescaled by k1 ----
    uint32_t afr[2][4][4];
    {
        const uint32_t* xb = g_srcb + (size_t)rbase * 32;
        #pragma unroll
        for (int t = 0; t < 2; ++t) {
            #pragma unroll
            for (int ks = 0; ks < 4; ++ks) {
                const uint32_t* p = xb + (t * 16 + g) * 32 + ks * 8 + (lane & 3);
                afr[t][ks][0] = p[0];
                afr[t][ks][1] = p[256];
                afr[t][ks][2] = p[4];
                afr[t][ks][3] = p[260];
                #pragma unroll
                for (int i = 0; i < 4; ++i) {
                    uint32_t u = afr[t][ks][i];
                    float lo = __uint_as_float(u << 16);
                    float hi = __uint_as_float(u & 0xFFFF0000u);
                    afr[t][ks][i] = cvt_bf16x2(lo * k1, hi * k1);
                }
            }
        }
    }

    // ldmatrix per-lane addresses (s-invariant swizzle)
    const int lr = lane & 7, lq = lane >> 3;
    const uint32_t lmoff0 = (uint32_t)(lr * 128 + ((lq * 16)       ^ (lr << 4)));
    const uint32_t lmoff1 = (uint32_t)(lr * 128 + (((lq + 4) * 16) ^ (lr << 4)));
    const int biasoff = (lane & 3) * 2;

    // f32 row-sum accumulators fed by the reduction MMA
    float acc0[4] = {0.f, 0.f, 0.f, 0.f};   // rows g, g+8
    float acc1[4] = {0.f, 0.f, 0.f, 0.f};   // rows g+16, g+24

    for (int t = tbeg; t < tend; ++t) {
        const int cur = (t - tbeg) & 1, nxt = cur ^ 1;
        const bool more = (t + 1 < tend);

        CP_WAIT0();
        __syncthreads();

        if (more) {
            int j0 = (t + 1) * TJ;
            uint32_t dst = smb + (uint32_t)(nxt * 16384);
            CP_ASYNC16(dst + d0, tgtb_bytes + (size_t)(j0 + r0) * 128 + c0 * 16);
            CP_ASYNC16(dst + d1, tgtb_bytes + (size_t)(j0 + r1) * 128 + c1 * 16);
            CP_COMMIT();
        }

        const uint32_t tadd = smb + (uint32_t)(cur * 16384);
        const float* bb = sbias + (t - tbeg) * TJ;
        #pragma unroll 2
        for (int sp = 0; sp < 8; ++sp) {
            uint32_t eA[4], eB[4];   // bf16x2 exps: A-fragments for reduction mma
            #pragma unroll
            for (int h = 0; h < 2; ++h) {
                const int s = sp * 2 + h;
                const float2 bp = *(const float2*)(bb + s * 8 + biasoff);
                const float bias4[4] = { bp.x, bp.y, bp.x, bp.y };
                float c0f[4], c1f[4];
                uint32_t bA[4], bB[4];
                ldm_x4(bA, tadd + s * 1024 + lmoff0);
                ldm_x4(bB, tadd + s * 1024 + lmoff1);
                // first k-step fuses bias via C-operand; rest accumulate
                mma16816_dc(c0f, afr[0][0], bA[0], bA[1], bias4);
                mma16816_dc(c1f, afr[1][0], bA[0], bA[1], bias4);
                mma16816(c0f, afr[0][1], bA[2], bA[3]);
                mma16816(c1f, afr[1][1], bA[2], bA[3]);
                mma16816(c0f, afr[0][2], bB[0], bB[1]);
                mma16816(c1f, afr[1][2], bB[0], bB[1]);
                mma16816(c0f, afr[0][3], bB[2], bB[3]);
                mma16816(c1f, afr[1][3], bB[2], bB[3]);

                // exp2 in f32 on MUFU (rt 8), then pack to bf16 for the reduction mma
                eA[h * 2 + 0] = cvt_bf16x2(ex2f(c0f[0]), ex2f(c0f[1]));   // row g
                eA[h * 2 + 1] = cvt_bf16x2(ex2f(c0f[2]), ex2f(c0f[3]));   // row g+8
                eB[h * 2 + 0] = cvt_bf16x2(ex2f(c1f[0]), ex2f(c1f[1]));   // row g+16
                eB[h * 2 + 1] = cvt_bf16x2(ex2f(c1f[2]), ex2f(c1f[3]));   // row g+24
            }
            // row-sum via tensor pipe: C[m,n] += sum_k E[m,k] * 1
            mma16816(acc0, eA, ONESF, ONESF);
            mma16816(acc1, eB, ONESF, ONESF);
        }
        __syncthreads();
    }

    // ---- per-row accumulation: acc[0]/acc[2] hold full row sums (4 lanes identical) ----
    if ((lane & 3) == 0) {
        atomicAdd(&g_rowsum[rbase + g],      acc0[0]);
        atomicAdd(&g_rowsum[rbase + 8 + g],  acc0[2]);
        atomicAdd(&g_rowsum[rbase + 16 + g], acc1[0]);
        atomicAdd(&g_rowsum[rbase + 24 + g], acc1[2]);
    }

    // ---- inline finalize: last CTA reduces all rows ----
    __syncthreads();
    if (tid == 0) {
        __threadfence();
        unsigned int old = atomicAdd(&g_done, 1u);
        smflag = (old == (unsigned int)(gridDim.x * gridDim.y - 1)) ? 1 : 0;
    }
    __syncthreads();
    if (smflag) {
        const float log_nu = -logf((float)M);
        double part = 0.0;
        for (int i = tid; i < N; i += THREADS) {
            float lse = -alpha * g_sqs[i] + log_nu + LN2 * (log2f(g_rowsum[i]) - SHIFT);
            part += (double)(-REGP * lse);
        }
        #pragma unroll
        for (int o = 16; o; o >>= 1) part += __shfl_xor_sync(0xffffffffu, part, o);
        if (lane == 0) atomicAdd(&g_result, part);
        __syncthreads();
        if (tid == 0)
            out[0] = (float)(g_result / (double)N + g_psi_sum / (double)M);
    }
}

extern "C" void kernel_launch(void* const* d_in, const int* in_sizes, int n_in,
                              void* d_out, int out_size) {
    const float* src = (const float*)d_in[0];   // [N, 64]
    const float* tgt = (const float*)d_in[1];   // [M, 64]
    const float* psi = (const float*)d_in[2];   // [M]
    int N = in_sizes[0] / DVAL;
    int M = in_sizes[2];

    k_pre<<<296, 256>>>(src, tgt, psi, N, M);

    dim3 grd(N / BLOCK_ROWS, JSPLIT);           // 16 x 9 = 144 CTAs, 1/SM
    k_main_mma<<<grd, THREADS>>>(psi, (float*)d_out, N, M);
}

// round 16
// speedup vs baseline: 2.2906x; 1.0050x over previous
#include <cuda_runtime.h>
#include <cuda_bf16.h>
#include <cstdint>

#define DVAL 64
#define MAXM 16384
#define MAXN 8192
#define REGP   0.05f
#define LOG2E  1.4426950408889634f
#define LN2    0.6931471805599453f
#define SHIFT  28.0f

#define THREADS 512          // 16 warps
#define BLOCK_ROWS 512       // 32 rows per warp
#define TJ 128               // j-tile
#define JSPLIT 9
#define MAXTILES 15          // ceil(128/9)

__device__ double g_cost_sum;
__device__ double g_psi_sum;
__device__ double g_result;
__device__ unsigned int g_done;
__device__ float  g_sqt[MAXM];
__device__ float  g_sqs[MAXN];
__device__ float  g_rowsum[MAXN];
__device__ uint32_t g_tgtb[MAXM * DVAL / 2];   // bf16x2 packed
__device__ uint32_t g_srcb[MAXN * DVAL / 2];

// ---------- helpers ----------
static __device__ __forceinline__ uint32_t cvt_bf16x2(float lo, float hi) {
    uint32_t r; asm("cvt.rn.bf16x2.f32 %0, %1, %2;" : "=r"(r) : "f"(hi), "f"(lo)); return r;
}
static __device__ __forceinline__ float ex2f(float x) {
    float r; asm("ex2.approx.ftz.f32 %0, %1;" : "=f"(r) : "f"(x)); return r;
}
// D += A*B (C == D)
static __device__ __forceinline__ void mma16816(float* c, const uint32_t* a, uint32_t b0, uint32_t b1) {
    asm("mma.sync.aligned.m16n8k16.row.col.f32.bf16.bf16.f32 "
        "{%0,%1,%2,%3}, {%4,%5,%6,%7}, {%8,%9}, {%0,%1,%2,%3};"
        : "+f"(c[0]), "+f"(c[1]), "+f"(c[2]), "+f"(c[3])
        : "r"(a[0]), "r"(a[1]), "r"(a[2]), "r"(a[3]), "r"(b0), "r"(b1));
}
// D = A*B + C (separate C: bias-fused first k-step)
static __device__ __forceinline__ void mma16816_dc(float* d, const uint32_t* a, uint32_t b0, uint32_t b1,
                                                   const float* c) {
    asm("mma.sync.aligned.m16n8k16.row.col.f32.bf16.bf16.f32 "
        "{%0,%1,%2,%3}, {%4,%5,%6,%7}, {%8,%9}, {%10,%11,%12,%13};"
        : "=f"(d[0]), "=f"(d[1]), "=f"(d[2]), "=f"(d[3])
        : "r"(a[0]), "r"(a[1]), "r"(a[2]), "r"(a[3]), "r"(b0), "r"(b1),
          "f"(c[0]), "f"(c[1]), "f"(c[2]), "f"(c[3]));
}
static __device__ __forceinline__ void ldm_x4(uint32_t* r, uint32_t addr) {
    asm volatile("ldmatrix.sync.aligned.m8n8.x4.shared.b16 {%0,%1,%2,%3}, [%4];"
        : "=r"(r[0]), "=r"(r[1]), "=r"(r[2]), "=r"(r[3]) : "r"(addr));
}
static __device__ __forceinline__ uint32_t smem_u32(const void* p) {
    uint32_t a;
    asm("{ .reg .u64 t; cvta.to.shared.u64 t, %1; cvt.u32.u64 %0, t; }" : "=r"(a) : "l"(p));
    return a;
}
#define CP_ASYNC16(dst, src) \
    asm volatile("cp.async.cg.shared.global [%0], [%1], 16;" :: "r"(dst), "l"(src) : "memory")
#define CP_COMMIT() asm volatile("cp.async.commit_group;" ::: "memory")
#define CP_WAIT0()  asm volatile("cp.async.wait_group 0;" ::: "memory")

// ---------------- kernel 1: convert + reductions + init ----------------
__global__ void k_pre(const float* __restrict__ src, const float* __restrict__ tgt,
                      const float* __restrict__ psi, int N, int M) {
    int gtid = blockIdx.x * blockDim.x + threadIdx.x;
    int nth  = gridDim.x * blockDim.x;
    int lane = threadIdx.x & 31;

    if (gtid == 0) { g_cost_sum = 0.0; g_psi_sum = 0.0; g_result = 0.0; g_done = 0u; }
    for (int i = gtid; i < N; i += nth) g_rowsum[i] = 0.0f;

    const float2* t2 = (const float2*)tgt;
    float cs = 0.0f;
    for (int i = gtid; i < M * 32; i += nth) {
        float2 v = t2[i];
        cs += v.x * v.x + v.y * v.y;
        g_tgtb[i] = cvt_bf16x2(v.x, v.y);
    }
    const float2* s2 = (const float2*)src;
    for (int i = gtid; i < N * 32; i += nth) {
        float2 v = s2[i];
        g_srcb[i] = cvt_bf16x2(v.x, v.y);
    }
    float pp = 0.0f;
    for (int i = gtid; i < M; i += nth) pp += psi[i];
    #pragma unroll
    for (int o = 16; o; o >>= 1) {
        cs += __shfl_xor_sync(0xffffffffu, cs, o);
        pp += __shfl_xor_sync(0xffffffffu, pp, o);
    }
    if (lane == 0) {
        atomicAdd(&g_cost_sum, (double)cs);
        if (pp != 0.0f) atomicAdd(&g_psi_sum, (double)pp);
    }

    // per-row squared norms, 4 lanes per row
    int grp = gtid >> 2, sub = gtid & 3, ngrp = nth >> 2;
    for (int row = grp; row < M + N; row += ngrp) {
        const float4* p = (row < M)
            ? (const float4*)(tgt + (size_t)row * DVAL)
            : (const float4*)(src + (size_t)(row - M) * DVAL);
        float s = 0.0f;
        #pragma unroll
        for (int q = 0; q < 4; ++q) {
            float4 v = p[sub + q * 4];
            s += v.x * v.x + v.y * v.y + v.z * v.z + v.w * v.w;
        }
        s += __shfl_xor_sync(0xffffffffu, s, 1);
        s += __shfl_xor_sync(0xffffffffu, s, 2);
        if (sub == 0) {
            if (row < M) g_sqt[row] = s; else g_sqs[row - M] = s;
        }
    }
}

// ---------------- kernel 2: main HMMA + f32 exp2 + scalar f32 accumulation ----------------
__global__ void __launch_bounds__(THREADS, 1)
k_main_mma(const float* __restrict__ psi, float* __restrict__ out, int N, int M) {
    __shared__ char sm[2 * 16384 + MAXTILES * TJ * 4];
    __shared__ int smflag;
    float* sbias = (float*)(sm + 32768);
    const uint32_t smb = smem_u32(sm);

    const int tid  = threadIdx.x;
    const int wid  = tid >> 5;
    const int lane = tid & 31;
    const int g    = lane >> 2;

    const int rbase = blockIdx.x * BLOCK_ROWS + wid * 32;

    const int TT = M / TJ;
    const int tbeg = (blockIdx.y * TT) / JSPLIT;
    const int tend = ((blockIdx.y + 1) * TT) / JSPLIT;
    const int jbase = tbeg * TJ;
    const int jcnt  = (tend - tbeg) * TJ;

    // per-thread cp.async chunk coords (2 chunks of 16B per thread)
    const int ch0 = tid,       r0 = ch0 >> 3, c0 = ch0 & 7;
    const int ch1 = tid + 512, r1 = ch1 >> 3, c1 = ch1 & 7;
    const uint32_t d0 = (uint32_t)((r0 * 128 + c0 * 16) ^ ((r0 & 7) << 4));
    const uint32_t d1 = (uint32_t)((r1 * 128 + c1 * 16) ^ ((r1 & 7) << 4));
    const char* tgtb_bytes = (const char*)g_tgtb;

    // ---- start tile 0 fill ----
    CP_ASYNC16(smb + d0, tgtb_bytes + (size_t)(jbase + r0) * 128 + c0 * 16);
    CP_ASYNC16(smb + d1, tgtb_bytes + (size_t)(jbase + r1) * 128 + c1 * 16);
    CP_COMMIT();

    const float cn = (float)(g_cost_sum / (double)M);
    const float alpha = 1.0f / (REGP * cn);
    const float k1 = 2.0f * LOG2E * alpha;

    // ---- bias for whole j-range into smem (overlaps cp.async) ----
    for (int jj = tid; jj < jcnt; jj += THREADS) {
        int j = jbase + jj;
        sbias[jj] = LOG2E * (psi[j] * (1.0f / REGP) - alpha * g_sqt[j]) + SHIFT;
    }

    // ---- A fragments from bf16 globals, prescaled by k1 ----
    uint32_t afr[2][4][4];
    {
        const uint32_t* xb = g_srcb + (size_t)rbase * 32;
        #pragma unroll
        for (int t = 0; t < 2; ++t) {
            #pragma unroll
            for (int ks = 0; ks < 4; ++ks) {
                const uint32_t* p = xb + (t * 16 + g) * 32 + ks * 8 + (lane & 3);
                afr[t][ks][0] = p[0];
                afr[t][ks][1] = p[256];
                afr[t][ks][2] = p[4];
                afr[t][ks][3] = p[260];
                #pragma unroll
                for (int i = 0; i < 4; ++i) {
                    uint32_t u = afr[t][ks][i];
                    float lo = __uint_as_float(u << 16);
                    float hi = __uint_as_float(u & 0xFFFF0000u);
                    afr[t][ks][i] = cvt_bf16x2(lo * k1, hi * k1);
                }
            }
        }
    }

    // ldmatrix per-lane addresses (s-invariant swizzle)
    const int lr = lane & 7, lq = lane >> 3;
    const uint32_t lmoff0 = (uint32_t)(lr * 128 + ((lq * 16)       ^ (lr << 4)));
    const uint32_t lmoff1 = (uint32_t)(lr * 128 + (((lq + 4) * 16) ^ (lr << 4)));
    const int biasoff = (lane & 3) * 2;

    // scalar f32 row-sum accumulators (per thread: 2 cols x 4 row-groups)
    float rs[8] = {0.f, 0.f, 0.f, 0.f, 0.f, 0.f, 0.f, 0.f};

    for (int t = tbeg; t < tend; ++t) {
        const int cur = (t - tbeg) & 1, nxt = cur ^ 1;
        const bool more = (t + 1 < tend);

        CP_WAIT0();
        __syncthreads();

        if (more) {
            int j0 = (t + 1) * TJ;
            uint32_t dst = smb + (uint32_t)(nxt * 16384);
            CP_ASYNC16(dst + d0, tgtb_bytes + (size_t)(j0 + r0) * 128 + c0 * 16);
            CP_ASYNC16(dst + d1, tgtb_bytes + (size_t)(j0 + r1) * 128 + c1 * 16);
            CP_COMMIT();
        }

        const uint32_t tadd = smb + (uint32_t)(cur * 16384);
        const float* bb = sbias + (t - tbeg) * TJ;
        #pragma unroll 4
        for (int s = 0; s < 16; ++s) {
            const float2 bp = *(const float2*)(bb + s * 8 + biasoff);
            const float bias4[4] = { bp.x, bp.y, bp.x, bp.y };
            float c0f[4], c1f[4];
            uint32_t bA[4], bB[4];
            ldm_x4(bA, tadd + s * 1024 + lmoff0);
            ldm_x4(bB, tadd + s * 1024 + lmoff1);
            // first k-step fuses bias via C-operand; rest accumulate
            mma16816_dc(c0f, afr[0][0], bA[0], bA[1], bias4);
            mma16816_dc(c1f, afr[1][0], bA[0], bA[1], bias4);
            mma16816(c0f, afr[0][1], bA[2], bA[3]);
            mma16816(c1f, afr[1][1], bA[2], bA[3]);
            mma16816(c0f, afr[0][2], bB[0], bB[1]);
            mma16816(c1f, afr[1][2], bB[0], bB[1]);
            mma16816(c0f, afr[0][3], bB[2], bB[3]);
            mma16816(c1f, afr[1][3], bB[2], bB[3]);

            // exp2 on MUFU, accumulate directly in f32 (no cvt, no reduction mma)
            rs[0] += ex2f(c0f[0]);
            rs[1] += ex2f(c0f[1]);
            rs[2] += ex2f(c0f[2]);
            rs[3] += ex2f(c0f[3]);
            rs[4] += ex2f(c1f[0]);
            rs[5] += ex2f(c1f[1]);
            rs[6] += ex2f(c1f[2]);
            rs[7] += ex2f(c1f[3]);
        }
        __syncthreads();
    }

    // ---- per-row accumulation: pair cols, reduce across the 4 lanes of each row ----
    {
        float s0 = rs[0] + rs[1];   // row g
        float s1 = rs[2] + rs[3];   // row g+8
        float s2 = rs[4] + rs[5];   // row g+16
        float s3 = rs[6] + rs[7];   // row g+24
        s0 += __shfl_xor_sync(0xffffffffu, s0, 1);
        s0 += __shfl_xor_sync(0xffffffffu, s0, 2);
        s1 += __shfl_xor_sync(0xffffffffu, s1, 1);
        s1 += __shfl_xor_sync(0xffffffffu, s1, 2);
        s2 += __shfl_xor_sync(0xffffffffu, s2, 1);
        s2 += __shfl_xor_sync(0xffffffffu, s2, 2);
        s3 += __shfl_xor_sync(0xffffffffu, s3, 1);
        s3 += __shfl_xor_sync(0xffffffffu, s3, 2);
        if ((lane & 3) == 0) {
            atomicAdd(&g_rowsum[rbase + g],      s0);
            atomicAdd(&g_rowsum[rbase + 8 + g],  s1);
            atomicAdd(&g_rowsum[rbase + 16 + g], s2);
            atomicAdd(&g_rowsum[rbase + 24 + g], s3);
        }
    }

    // ---- inline finalize: last CTA reduces all rows ----
    __syncthreads();
    if (tid == 0) {
        __threadfence();
        unsigned int old = atomicAdd(&g_done, 1u);
        smflag = (old == (unsigned int)(gridDim.x * gridDim.y - 1)) ? 1 : 0;
    }
    __syncthreads();
    if (smflag) {
        const float log_nu = -logf((float)M);
        double part = 0.0;
        for (int i = tid; i < N; i += THREADS) {
            float lse = -alpha * g_sqs[i] + log_nu + LN2 * (log2f(g_rowsum[i]) - SHIFT);
            part += (double)(-REGP * lse);
        }
        #pragma unroll
        for (int o = 16; o; o >>= 1) part += __shfl_xor_sync(0xffffffffu, part, o);
        if (lane == 0) atomicAdd(&g_result, part);
        __syncthreads();
        if (tid == 0)
            out[0] = (float)(g_result / (double)N + g_psi_sum / (double)M);
    }
}

extern "C" void kernel_launch(void* const* d_in, const int* in_sizes, int n_in,
                              void* d_out, int out_size) {
    const float* src = (const float*)d_in[0];   // [N, 64]
    const float* tgt = (const float*)d_in[1];   // [M, 64]
    const float* psi = (const float*)d_in[2];   // [M]
    int N = in_sizes[0] / DVAL;
    int M = in_sizes[2];

    k_pre<<<592, 256>>>(src, tgt, psi, N, M);

    dim3 grd(N / BLOCK_ROWS, JSPLIT);           // 16 x 9 = 144 CTAs, 1/SM
    k_main_mma<<<grd, THREADS>>>(psi, (float*)d_out, N, M);
}